// round 5
// baseline (speedup 1.0000x reference)
#include <cuda_runtime.h>
#include <cuda_fp16.h>
#include <cstdint>

#define EKV 30016
__device__ float  d_E[EKV];              // E[v] = embedding[v] . context_weight (fp32)
__device__ __half d_EH[EKV * 128];       // fp16 shadow of the embedding table

typedef unsigned long long u64;

static __device__ __forceinline__ u64 pack2(float x, float y) {
    u64 r; asm("mov.b64 %0,{%1,%2};" : "=l"(r) : "f"(x), "f"(y)); return r;
}
static __device__ __forceinline__ float2 unpack2(u64 v) {
    float2 f; asm("mov.b64 {%0,%1},%2;" : "=f"(f.x), "=f"(f.y) : "l"(v)); return f;
}
static __device__ __forceinline__ void fma2(u64& d, u64 a, u64 b) {
    asm("fma.rn.f32x2 %0,%1,%2,%0;" : "+l"(d) : "l"(a), "l"(b));
}
static __device__ __forceinline__ void mul2(u64& d, u64 a) {
    asm("mul.rn.f32x2 %0,%0,%1;" : "+l"(d) : "l"(a));
}

static __device__ __forceinline__ float wsum(float v) {
#pragma unroll
    for (int o = 16; o; o >>= 1) v += __shfl_xor_sync(0xffffffffu, v, o);
    return v;
}
static __device__ __forceinline__ float wmax(float v) {
#pragma unroll
    for (int o = 16; o; o >>= 1) v = fmaxf(v, __shfl_xor_sync(0xffffffffu, v, o));
    return v;
}

// Pre-kernel: E[v] = emb[v].cw (fp32) and d_EH[v] = fp16(emb[v]). One warp/row.
__global__ void ek_kernel(const float* __restrict__ emb,
                          const float* __restrict__ cw, int V) {
    int w = (blockIdx.x * blockDim.x + threadIdx.x) >> 5;
    int lane = threadIdx.x & 31;
    if (w >= V || w >= EKV) return;
    float4 e = reinterpret_cast<const float4*>(emb)[w * 32 + lane];
    float4 c = reinterpret_cast<const float4*>(cw)[lane];
    __half2 h0 = __floats2half2_rn(e.x, e.y);
    __half2 h1 = __floats2half2_rn(e.z, e.w);
    uint2 pk;
    pk.x = *reinterpret_cast<uint32_t*>(&h0);
    pk.y = *reinterpret_cast<uint32_t*>(&h1);
    reinterpret_cast<uint2*>(d_EH)[w * 32 + lane] = pk;
    float s = wsum(e.x * c.x + e.y * c.y + e.z * c.z + e.w * c.w);
    if (lane == 0) d_E[w] = s;
}

// 8-dim fp16 -> packed-f32x2 fused multiply-accumulate (4x FFMA2)
static __device__ __forceinline__ void acc8p(u64& q0, u64& q1, u64& q2, u64& q3,
                                             const uint4& pk, u64 cc) {
    float2 f0 = __half22float2(*reinterpret_cast<const __half2*>(&pk.x));
    float2 f1 = __half22float2(*reinterpret_cast<const __half2*>(&pk.y));
    float2 f2 = __half22float2(*reinterpret_cast<const __half2*>(&pk.z));
    float2 f3 = __half22float2(*reinterpret_cast<const __half2*>(&pk.w));
    fma2(q0, pack2(f0.x, f0.y), cc);
    fma2(q1, pack2(f1.x, f1.y), cc);
    fma2(q2, pack2(f2.x, f2.y), cc);
    fma2(q3, pack2(f3.x, f3.y), cc);
}

// Main kernel: one warp per tree. Gather: 16 lanes per fp16 row (LDG.128/lane),
// two slots per warp-iteration; packed f32x2 accumulators; occupancy-capped.
__global__ __launch_bounds__(256, 5) void tree_kernel(
    const int* __restrict__ tokens, const int* __restrict__ masks,
    float* __restrict__ out, int N, int V) {
    const unsigned F = 0xffffffffu;
    const int lane = threadIdx.x & 31;
    const int hl = lane & 15;       // position within half-warp (dim group)
    const int hs = lane >> 4;       // 0: even slots, 1: odd slots
    const int n = blockIdx.x * (blockDim.x >> 5) + (threadIdx.x >> 5);
    if (n >= N) return;
    const int vmax = min(V, EKV) - 1;
    const int* tk = tokens + n * 320;
    const int* mk = masks + n * 320;
    const uint4* eh4 = reinterpret_cast<const uint4*>(d_EH);

    // ---------- leaf level d = 7 ----------
    int t0 = tk[7 * 40 + lane];
    bool m0 = mk[7 * 40 + lane] != 0;
    bool v0 = m0 && (t0 >= 0);
    t0 = min(max(t0, 0), vmax);
    int t1 = 0; bool m1 = false, v1 = false;
    if (lane < 8) {
        t1 = tk[7 * 40 + 32 + lane];
        m1 = mk[7 * 40 + 32 + lane] != 0;
        v1 = m1 && (t1 >= 0);
        t1 = min(max(t1, 0), vmax);
    }
    int prev_cnt = __popc(__ballot_sync(F, m0)) +
                   __popc(__ballot_sync(F, (lane < 8) && m1));

    float c0 = v0 ? 1.f : 0.f;
    float c1 = v1 ? 1.f : 0.f;

    u64 q0 = 0, q1 = 0, q2 = 0, q3 = 0;   // packed f32x2 accumulators (8 dims)
#pragma unroll
    for (int s = 0; s < 16; ++s) {           // slots 0..31
        int slot = 2 * s + hs;
        float cs = __shfl_sync(F, c0, slot);
        int   ts = __shfl_sync(F, t0, slot);
        uint4 pk = eh4[ts * 16 + hl];
        acc8p(q0, q1, q2, q3, pk, pack2(cs, cs));
    }
#pragma unroll
    for (int s = 16; s < 20; ++s) {          // slots 32..39
        int slot = 2 * s + hs - 32;          // 0..7
        float cs = __shfl_sync(F, c1, slot);
        int   ts = __shfl_sync(F, t1, slot);
        uint4 pk = eh4[ts * 16 + hl];
        acc8p(q0, q1, q2, q3, pk, pack2(cs, cs));
    }
    // p = pooled . cw = sum over valid slots of E[token]
    float e0 = d_E[t0];
    float e1 = (lane < 8) ? d_E[t1] : 0.f;
    float p = wsum((v0 ? e0 : 0.f) + (v1 ? e1 : 0.f));

    // ---------- levels d = 6 .. 0 ----------
#pragma unroll 1
    for (int d = 6; d >= 0; --d) {
        t0 = tk[d * 40 + lane];
        m0 = mk[d * 40 + lane] != 0;
        v0 = m0 && (t0 >= 0);
        t0 = min(max(t0, 0), vmax);
        t1 = 0; m1 = false; v1 = false;
        if (lane < 8) {
            t1 = tk[d * 40 + 32 + lane];
            m1 = mk[d * 40 + 32 + lane] != 0;
            v1 = m1 && (t1 >= 0);
            t1 = min(max(t1, 0), vmax);
        }
        int cur_cnt = __popc(__ballot_sync(F, m0)) +
                      __popc(__ballot_sync(F, (lane < 8) && m1));
        int nc = max(prev_cnt, 1);   // child count = masks of level d+1
        prev_cnt = cur_cnt;

        e0 = d_E[t0];
        e1 = (lane < 8) ? d_E[t1] : 0.f;
        float g0 = 1.f / (1.f + __expf(-e0));
        float g1 = 1.f / (1.f + __expf(-e1));
        float cc0 = (v0 && (lane < nc)) ? g0 : 0.f;          // gate * child
        float cc1 = (v1 && (32 + lane < nc)) ? g1 : 0.f;
        float h0 = e0 + cc0 * p;                             // attn logit
        float h1 = e1 + cc1 * p;
        float l0 = v0 ? h0 : -1e38f;
        float l1 = v1 ? h1 : -1e38f;
        float mx = wmax(fmaxf(l0, l1));
        float x0 = v0 ? __expf(h0 - mx) : 0.f;
        float x1 = v1 ? __expf(h1 - mx) : 0.f;
        float Z = wsum(x0 + x1);
        float inv = 1.f / Z;
        float a0 = x0 * inv, a1 = x1 * inv;                  // softmax weights
        float A  = wsum(a0 * cc0 + a1 * cc1);                // Σ a_s cc_s
        float pn = wsum(a0 * h0 + a1 * h1);                  // new pooled . cw

        u64 Ap = pack2(A, A);
        mul2(q0, Ap); mul2(q1, Ap); mul2(q2, Ap); mul2(q3, Ap);
#pragma unroll
        for (int s = 0; s < 16; ++s) {       // slots 0..31
            int slot = 2 * s + hs;
            float cs = __shfl_sync(F, a0, slot);
            int   ts = __shfl_sync(F, t0, slot);
            uint4 pk = eh4[ts * 16 + hl];
            acc8p(q0, q1, q2, q3, pk, pack2(cs, cs));
        }
#pragma unroll
        for (int s = 16; s < 20; ++s) {      // slots 32..39
            int slot = 2 * s + hs - 32;
            float cs = __shfl_sync(F, a1, slot);
            int   ts = __shfl_sync(F, t1, slot);
            uint4 pk = eh4[ts * 16 + hl];
            acc8p(q0, q1, q2, q3, pk, pack2(cs, cs));
        }
        p = pn;
    }

    // Combine even/odd-slot halves (lane <-> lane^16), then lanes 0-15 store.
    float2 r0 = unpack2(q0), r1 = unpack2(q1), r2 = unpack2(q2), r3 = unpack2(q3);
    float4 accA = make_float4(r0.x, r0.y, r1.x, r1.y);
    float4 accB = make_float4(r2.x, r2.y, r3.x, r3.y);
    accA.x += __shfl_xor_sync(F, accA.x, 16);
    accA.y += __shfl_xor_sync(F, accA.y, 16);
    accA.z += __shfl_xor_sync(F, accA.z, 16);
    accA.w += __shfl_xor_sync(F, accA.w, 16);
    accB.x += __shfl_xor_sync(F, accB.x, 16);
    accB.y += __shfl_xor_sync(F, accB.y, 16);
    accB.z += __shfl_xor_sync(F, accB.z, 16);
    accB.w += __shfl_xor_sync(F, accB.w, 16);
    if (lane < 16) {
        float4* o4 = reinterpret_cast<float4*>(out) + n * 32 + hl * 2;
        o4[0] = accA;
        o4[1] = accB;
    }
}

extern "C" void kernel_launch(void* const* d_in, const int* in_sizes, int n_in,
                              void* d_out, int out_size) {
    const int*   tokens = (const int*)d_in[0];
    const int*   masks  = (const int*)d_in[1];   // bool -> int32 on the wire
    const float* emb    = (const float*)d_in[2];
    const float* cw     = (const float*)d_in[3];
    float*       out    = (float*)d_out;

    int V = in_sizes[2] / 128;          // vocab rows
    int N = in_sizes[0] / 320;          // trees (8*40 tokens each)

    ek_kernel<<<(V + 7) / 8, 256>>>(emb, cw, V);
    tree_kernel<<<(N + 7) / 8, 256>>>(tokens, masks, out, N, V);
}

// round 6
// speedup vs baseline: 1.4143x; 1.4143x over previous
#include <cuda_runtime.h>
#include <cuda_fp16.h>
#include <cstdint>

#define EKV 30016
__device__ float  d_E[EKV];              // E[v] = embedding[v] . context_weight (fp32)
__device__ __half d_EH[EKV * 128];       // fp16 shadow of the embedding table

static __device__ __forceinline__ float wsum(float v) {
#pragma unroll
    for (int o = 16; o; o >>= 1) v += __shfl_xor_sync(0xffffffffu, v, o);
    return v;
}
static __device__ __forceinline__ float wmax(float v) {
#pragma unroll
    for (int o = 16; o; o >>= 1) v = fmaxf(v, __shfl_xor_sync(0xffffffffu, v, o));
    return v;
}

// Pre-kernel: E[v] = emb[v].cw (fp32) and d_EH[v] = fp16(emb[v]). One warp/row.
__global__ void ek_kernel(const float* __restrict__ emb,
                          const float* __restrict__ cw, int V) {
    int w = (blockIdx.x * blockDim.x + threadIdx.x) >> 5;
    int lane = threadIdx.x & 31;
    if (w >= V || w >= EKV) return;
    float4 e = reinterpret_cast<const float4*>(emb)[w * 32 + lane];
    float4 c = reinterpret_cast<const float4*>(cw)[lane];
    __half2 h0 = __floats2half2_rn(e.x, e.y);
    __half2 h1 = __floats2half2_rn(e.z, e.w);
    uint2 pk;
    pk.x = *reinterpret_cast<uint32_t*>(&h0);
    pk.y = *reinterpret_cast<uint32_t*>(&h1);
    reinterpret_cast<uint2*>(d_EH)[w * 32 + lane] = pk;
    float s = wsum(e.x * c.x + e.y * c.y + e.z * c.z + e.w * c.w);
    if (lane == 0) d_E[w] = s;
}

// Main kernel, two phases per warp (one warp per tree):
//  Phase 1: scalar recursion (E-gathers + softmax) -> per-slot (token, weight)
//           staged in smem; prefix products of A folded in afterwards.
//  Phase 2: flat dependency-free 160-iter weighted gather of fp16 rows,
//           16 lanes per row (LDG.128/lane), 2 rows per warp-iteration.
__global__ __launch_bounds__(256) void tree_kernel(
    const int* __restrict__ tokens, const int* __restrict__ masks,
    float* __restrict__ out, int N, int V) {
    __shared__ int2 s_tw[8][320];
    const unsigned F = 0xffffffffu;
    const int lane = threadIdx.x & 31;
    const int wid = threadIdx.x >> 5;
    const int hl = lane & 15;       // dim group within half-warp
    const int hs = lane >> 4;       // 0: even rows, 1: odd rows
    const int n = blockIdx.x * 8 + wid;
    if (n >= N) return;
    const int vmax = min(V, EKV) - 1;
    const int* tk = tokens + n * 320;
    const int* mk = masks + n * 320;
    int2* tw = s_tw[wid];

    // ================= Phase 1: scalar recursion =================
    // leaf level d = 7
    int t0 = tk[7 * 40 + lane];
    bool m0 = mk[7 * 40 + lane] != 0;
    bool v0 = m0 && (t0 >= 0);
    t0 = min(max(t0, 0), vmax);
    int t1 = 0; bool m1 = false, v1 = false;
    if (lane < 8) {
        t1 = tk[7 * 40 + 32 + lane];
        m1 = mk[7 * 40 + 32 + lane] != 0;
        v1 = m1 && (t1 >= 0);
        t1 = min(max(t1, 0), vmax);
    }
    int prev_cnt = __popc(__ballot_sync(F, m0)) +
                   __popc(__ballot_sync(F, (lane < 8) && m1));

    tw[7 * 40 + lane] = make_int2(t0, __float_as_int(v0 ? 1.f : 0.f));
    if (lane < 8)
        tw[7 * 40 + 32 + lane] = make_int2(t1, __float_as_int(v1 ? 1.f : 0.f));

    float e0 = d_E[t0];
    float e1 = (lane < 8) ? d_E[t1] : 0.f;
    float p = wsum((v0 ? e0 : 0.f) + (v1 ? e1 : 0.f));

    float A_arr[7];
#pragma unroll
    for (int d = 6; d >= 0; --d) {
        t0 = tk[d * 40 + lane];
        m0 = mk[d * 40 + lane] != 0;
        v0 = m0 && (t0 >= 0);
        t0 = min(max(t0, 0), vmax);
        t1 = 0; m1 = false; v1 = false;
        if (lane < 8) {
            t1 = tk[d * 40 + 32 + lane];
            m1 = mk[d * 40 + 32 + lane] != 0;
            v1 = m1 && (t1 >= 0);
            t1 = min(max(t1, 0), vmax);
        }
        int cur_cnt = __popc(__ballot_sync(F, m0)) +
                      __popc(__ballot_sync(F, (lane < 8) && m1));
        int nc = max(prev_cnt, 1);   // child count = masks of level d+1
        prev_cnt = cur_cnt;

        e0 = d_E[t0];
        e1 = (lane < 8) ? d_E[t1] : 0.f;
        float g0 = 1.f / (1.f + __expf(-e0));
        float g1 = 1.f / (1.f + __expf(-e1));
        float cc0 = (v0 && (lane < nc)) ? g0 : 0.f;          // gate * child
        float cc1 = (v1 && (32 + lane < nc)) ? g1 : 0.f;
        float h0 = e0 + cc0 * p;                             // attn logit
        float h1 = e1 + cc1 * p;
        float l0 = v0 ? h0 : -1e38f;
        float l1 = v1 ? h1 : -1e38f;
        float mx = wmax(fmaxf(l0, l1));
        float x0 = v0 ? __expf(h0 - mx) : 0.f;
        float x1 = v1 ? __expf(h1 - mx) : 0.f;
        float Z = wsum(x0 + x1);
        float inv = 1.f / Z;
        float a0 = x0 * inv, a1 = x1 * inv;                  // softmax weights
        A_arr[d] = wsum(a0 * cc0 + a1 * cc1);                // Σ a_s cc_s
        p = wsum(a0 * h0 + a1 * h1);                         // new pooled . cw

        tw[d * 40 + lane] = make_int2(t0, __float_as_int(a0));
        if (lane < 8)
            tw[d * 40 + 32 + lane] = make_int2(t1, __float_as_int(a1));
    }

    // Fold prefix products Prefix[d] = Π_{j<d} A[j] into stored weights
    // (same-lane smem entries -> no sync needed).
    float pref = 1.f;
#pragma unroll
    for (int d = 1; d < 8; ++d) {
        pref *= A_arr[d - 1];
        int2 e = tw[d * 40 + lane];
        tw[d * 40 + lane] =
            make_int2(e.x, __float_as_int(__int_as_float(e.y) * pref));
        if (lane < 8) {
            int2 e2 = tw[d * 40 + 32 + lane];
            tw[d * 40 + 32 + lane] =
                make_int2(e2.x, __float_as_int(__int_as_float(e2.y) * pref));
        }
    }
    __syncwarp();   // phase 2 reads other lanes' entries

    // ================= Phase 2: flat weighted gather =================
    const uint4* eh4 = reinterpret_cast<const uint4*>(d_EH);
    float4 accA = make_float4(0.f, 0.f, 0.f, 0.f);
    float4 accB = make_float4(0.f, 0.f, 0.f, 0.f);
#pragma unroll 4
    for (int it = 0; it < 160; ++it) {
        int2 e = tw[2 * it + hs];           // LDS.64 broadcast per half-warp
        float cs = __int_as_float(e.y);
        uint4 pk = eh4[e.x * 16 + hl];      // LDG.128: 8 fp16 dims
        float2 f0 = __half22float2(*reinterpret_cast<const __half2*>(&pk.x));
        float2 f1 = __half22float2(*reinterpret_cast<const __half2*>(&pk.y));
        float2 f2 = __half22float2(*reinterpret_cast<const __half2*>(&pk.z));
        float2 f3 = __half22float2(*reinterpret_cast<const __half2*>(&pk.w));
        accA.x = fmaf(cs, f0.x, accA.x); accA.y = fmaf(cs, f0.y, accA.y);
        accA.z = fmaf(cs, f1.x, accA.z); accA.w = fmaf(cs, f1.y, accA.w);
        accB.x = fmaf(cs, f2.x, accB.x); accB.y = fmaf(cs, f2.y, accB.y);
        accB.z = fmaf(cs, f3.x, accB.z); accB.w = fmaf(cs, f3.y, accB.w);
    }

    // Combine even/odd-row halves (lane <-> lane^16), lanes 0-15 store.
    accA.x += __shfl_xor_sync(F, accA.x, 16);
    accA.y += __shfl_xor_sync(F, accA.y, 16);
    accA.z += __shfl_xor_sync(F, accA.z, 16);
    accA.w += __shfl_xor_sync(F, accA.w, 16);
    accB.x += __shfl_xor_sync(F, accB.x, 16);
    accB.y += __shfl_xor_sync(F, accB.y, 16);
    accB.z += __shfl_xor_sync(F, accB.z, 16);
    accB.w += __shfl_xor_sync(F, accB.w, 16);
    if (lane < 16) {
        float4* o4 = reinterpret_cast<float4*>(out) + n * 32 + hl * 2;
        o4[0] = accA;
        o4[1] = accB;
    }
}

extern "C" void kernel_launch(void* const* d_in, const int* in_sizes, int n_in,
                              void* d_out, int out_size) {
    const int*   tokens = (const int*)d_in[0];
    const int*   masks  = (const int*)d_in[1];   // bool -> int32 on the wire
    const float* emb    = (const float*)d_in[2];
    const float* cw     = (const float*)d_in[3];
    float*       out    = (float*)d_out;

    int V = in_sizes[2] / 128;          // vocab rows
    int N = in_sizes[0] / 320;          // trees (8*40 tokens each)

    ek_kernel<<<(V + 7) / 8, 256>>>(emb, cw, V);
    tree_kernel<<<(N + 7) / 8, 256>>>(tokens, masks, out, N, V);
}